// round 11
// baseline (speedup 1.0000x reference)
#include <cuda_runtime.h>
#include <cuda_bf16.h>
#include <math.h>

// ---------------- configuration ----------------
constexpr int S   = 192;                 // input cube side
constexpr int SD  = S * S;
constexpr size_t CS = (size_t)S * S * S; // channel stride
constexpr int OUT = 191;                 // output grid side

constexpr int TW = 32;                   // output cols per block (2 per warp)
constexpr int TH = 29;                   // output rows per block (32 input rows = 32 lanes)
constexpr int NWARP = TW / 2;            // 16 warps
constexpr int NT = NWARP * 32;           // 512 threads
constexpr int INC = 35;                  // input cols per block: w0-1 .. w0+33
constexpr int NPL = 32 * INC;            // 1120 floats per channel plane-tile
constexpr int DCH = 7, DPER = 28;        // 7 depth chunks x 28 outputs
constexpr int GX = 6, GY = 7;            // 6*32>=191, 7*29>=191
constexpr int NBLOCKS = GX * GY * DCH;   // 294

__device__ double g_part[NBLOCKS];

__global__ void finalize_kernel(float* out) {
    __shared__ double wsum[8];
    int tid = threadIdx.x;
    double s = 0.0;
    for (int i = tid; i < NBLOCKS; i += 256) s += g_part[i];
#pragma unroll
    for (int o = 16; o > 0; o >>= 1) s += __shfl_down_sync(0xffffffffu, s, o);
    int lane = tid & 31, warp = tid >> 5;
    if (lane == 0) wsum[warp] = s;
    __syncthreads();
    if (warp == 0) {
        double v = (lane < 8) ? wsum[lane] : 0.0;
#pragma unroll
        for (int o = 4; o > 0; o >>= 1) v += __shfl_down_sync(0xffffffffu, v, o);
        if (lane == 0) out[0] = (float)(v / ((double)OUT * OUT * OUT));
    }
}

__global__ __launch_bounds__(NT, 1)
void nh_kernel(const float* __restrict__ yp)
{
    __shared__ float s_in[2][3 * NPL];   // ping-pong input plane tiles (3 channels)
    __shared__ float s_red[NT / 32];

    const int tid  = threadIdx.x;
    const int lane = tid & 31;           // lane = input row index (h0-1+lane)
    const int g    = tid >> 5;           // warp = W-pair: outputs w0+2g, w0+2g+1
    const int w0   = blockIdx.x * TW;
    const int h0   = blockIdx.y * TH;
    const int od0  = blockIdx.z * DPER;
    const int od1  = min(OUT, od0 + DPER);

    // ---- fixed masks ----
    const int qh = h0 - 1 + lane;                     // diff row of this lane
    const float mh = (qh >= 0 && qh < OUT) ? 1.f : 0.f;
    float mm[4];                                      // per-diff-column mask * mh
#pragma unroll
    for (int i = 0; i < 4; ++i) {
        int qw = w0 - 1 + 2 * g + i;
        mm[i] = (qw >= 0 && qw < OUT) ? mh : 0.f;
    }
    const bool eh = (lane < TH) && (h0 + lane < OUT);
    const float ew0 = (eh && (w0 + 2 * g     < OUT)) ? 1.f : 0.f;
    const float ew1 = (eh && (w0 + 2 * g + 1 < OUT)) ? 1.f : 0.f;

    // ---- plane loader: global plane p -> s_in[p&1] (zero-padded) ----
    auto load_plane = [&](int p) {
        float* dst = s_in[p & 1];
        const float* src = yp + (size_t)p * SD;
        for (int l = tid; l < 3 * NPL; l += NT) {
            int ch  = l / NPL;
            int rem = l - ch * NPL;
            int r   = rem / INC;
            int wc  = rem - r * INC;
            int gh = h0 - 1 + r, gw = w0 - 1 + wc;
            float v = 0.f;
            if ((unsigned)gh < (unsigned)S && (unsigned)gw < (unsigned)S)
                v = src[(size_t)ch * CS + gh * S + gw];
            dst[l] = v;
        }
    };
    // read this thread's 5-col row segment per channel from plane buffer pb
    auto read_row = [&](int pb, float c[3][5]) {
#pragma unroll
        for (int ch = 0; ch < 3; ++ch) {
            const float* q = &s_in[pb][ch * NPL + lane * INC + 2 * g];
#pragma unroll
            for (int i = 0; i < 5; ++i) c[ch][i] = q[i];
        }
    };

    // rolling state: psX[(ch*3+t)*2 + o], t: 0=D-diff,1=H-diff,2=W-diff, o=output col
    float psA[18], psB[18];
#pragma unroll
    for (int r = 0; r < 18; ++r) { psA[r] = 0.f; psB[r] = 0.f; }

    float a[3][5];                       // current plane (depth dd) row values
#pragma unroll
    for (int ch = 0; ch < 3; ++ch)
#pragma unroll
        for (int i = 0; i < 5; ++i) a[ch][i] = 0.f;

    if (od0 > 0) {                       // preload plane od0-1 into a-regs
        load_plane(od0 - 1);
        __syncthreads();
        read_row((od0 - 1) & 1, a);
        // next load targets buffer od0&1 (the other one) -> no extra sync needed
    }

    float acc = 0.f;
    const float inv27 = 1.f / 27.f;

    for (int dd = od0 - 1; dd <= od1; ++dd) {
        const int p = dd + 1;            // plane needed for D-diff at depth dd
        if (p < S) load_plane(p);
        __syncthreads();

        float cc[3][5];
        if (p < S) read_row(p & 1, cc);
        else {
#pragma unroll
            for (int ch = 0; ch < 3; ++ch)
#pragma unroll
                for (int i = 0; i < 5; ++i) cc[ch][i] = 0.f;
        }

        // ---- per-depth plane sums (W-sum in regs, H-sum via shuffles) ----
        float psC[18];
        const bool dok = (dd >= 0) && (dd < OUT);   // uniform across block
        if (dok) {
#pragma unroll
            for (int ch = 0; ch < 3; ++ch) {
                float b0 = __shfl_down_sync(0xffffffffu, a[ch][0], 1);
                float b1 = __shfl_down_sync(0xffffffffu, a[ch][1], 1);
                float b2 = __shfl_down_sync(0xffffffffu, a[ch][2], 1);
                float b3 = __shfl_down_sync(0xffffffffu, a[ch][3], 1);
                // masked diffs at diff-cols j = 2g..2g+3
                float dD0 = mm[0] * fabsf(cc[ch][0] - a[ch][0]);
                float dD1 = mm[1] * fabsf(cc[ch][1] - a[ch][1]);
                float dD2 = mm[2] * fabsf(cc[ch][2] - a[ch][2]);
                float dD3 = mm[3] * fabsf(cc[ch][3] - a[ch][3]);
                float dH0 = mm[0] * fabsf(b0 - a[ch][0]);
                float dH1 = mm[1] * fabsf(b1 - a[ch][1]);
                float dH2 = mm[2] * fabsf(b2 - a[ch][2]);
                float dH3 = mm[3] * fabsf(b3 - a[ch][3]);
                float dW0 = mm[0] * fabsf(a[ch][1] - a[ch][0]);
                float dW1 = mm[1] * fabsf(a[ch][2] - a[ch][1]);
                float dW2 = mm[2] * fabsf(a[ch][3] - a[ch][2]);
                float dW3 = mm[3] * fabsf(a[ch][4] - a[ch][3]);
                // W 3-tap sums for the 2 outputs
                float cD = dD1 + dD2, cH = dH1 + dH2, cW = dW1 + dW2;
                psC[(ch * 3 + 0) * 2 + 0] = cD + dD0;
                psC[(ch * 3 + 0) * 2 + 1] = cD + dD3;
                psC[(ch * 3 + 1) * 2 + 0] = cH + dH0;
                psC[(ch * 3 + 1) * 2 + 1] = cH + dH3;
                psC[(ch * 3 + 2) * 2 + 0] = cW + dW0;
                psC[(ch * 3 + 2) * 2 + 1] = cW + dW3;
            }
            // H 3-tap sum via shuffles (result lives at output row = lane)
#pragma unroll
            for (int r = 0; r < 18; ++r) {
                float v  = psC[r];
                float u1 = __shfl_down_sync(0xffffffffu, v, 1);
                float u2 = __shfl_down_sync(0xffffffffu, v, 2);
                psC[r] = v + u1 + u2;
            }
        } else {
#pragma unroll
            for (int r = 0; r < 18; ++r) psC[r] = 0.f;
        }

        // ---- emit output depth d = dd-1 ----
        if (dd - 1 >= od0) {             // uniform branch
#pragma unroll
            for (int o = 0; o < 2; ++o) {
                float f[9];
#pragma unroll
                for (int r = 0; r < 9; ++r)
                    f[r] = (psA[r * 2 + o] + psB[r * 2 + o] + psC[r * 2 + o]) * inv27;
                // channel->role (reference): fx=filt(H-diff), fy=filt(D-diff), fz=filt(W-diff)
                float dxdx = f[4], dydx = f[1], dzdx = f[7];
                float dxdy = f[3], dydy = f[0], dzdy = f[6];
                float dxdz = f[5], dydz = f[2], dzdz = f[8];
                float a11 = dxdx + 1.f, a22 = dydy + 1.f, a33 = dzdz + 1.f;
                float J = a11 * (a22 * a33 - dydz * dzdy)
                        - dxdy * (dydx * a33 - dydz * dzdx)
                        + dxdz * (dydx * dzdy - a22 * dzdx);
                float Tr = a11 * a11 + dxdy * dxdy + dxdz * dxdz
                         + dydx * dydx + a22 * a22 + dydz * dydz
                         + dzdx * dzdx + dzdy * dzdy + a33 * a33;
                float stretch = Tr * __expf(1.f - J) - 3.f;
                float jm1 = J - 1.f;
                // mu=1, lam=5; mu<-1/6; lam<-5/(5+1/6)=30/31 => mu/2=1/12, lam/2=15/31
                float U = (1.f / 12.f) * stretch + (15.f / 31.f) * (jm1 * jm1);
                acc += (o == 0 ? ew0 : ew1) * U;
            }
        }

        // ---- roll ----
#pragma unroll
        for (int r = 0; r < 18; ++r) { psA[r] = psB[r]; psB[r] = psC[r]; }
#pragma unroll
        for (int ch = 0; ch < 3; ++ch)
#pragma unroll
            for (int i = 0; i < 5; ++i) a[ch][i] = cc[ch][i];
    }

    // ---- block reduction -> per-block partial ----
#pragma unroll
    for (int o = 16; o > 0; o >>= 1)
        acc += __shfl_down_sync(0xffffffffu, acc, o);
    int warp = tid >> 5;
    if (lane == 0) s_red[warp] = acc;
    __syncthreads();
    if (warp == 0) {
        float v = (lane < NT / 32) ? s_red[lane] : 0.f;
#pragma unroll
        for (int o = 8; o > 0; o >>= 1)
            v += __shfl_down_sync(0xffffffffu, v, o);
        if (lane == 0) {
            int bid = blockIdx.x + GX * (blockIdx.y + GY * blockIdx.z);
            g_part[bid] = (double)v;
        }
    }
}

extern "C" void kernel_launch(void* const* d_in, const int* in_sizes, int n_in,
                              void* d_out, int out_size)
{
    const float* yp = (const float*)d_in[0];   // y_pred [1,3,192,192,192]
    float* out = (float*)d_out;                // scalar output

    dim3 grid(GX, GY, DCH);                    // 6 x 7 x 7 = 294 blocks
    nh_kernel<<<grid, NT>>>(yp);
    finalize_kernel<<<1, 256>>>(out);
}

// round 12
// speedup vs baseline: 1.1487x; 1.1487x over previous
#include <cuda_runtime.h>
#include <cuda_bf16.h>
#include <math.h>

// ---------------- configuration ----------------
constexpr int S   = 192;                  // input cube side
constexpr int SD  = S * S;
constexpr size_t CS = (size_t)S * S * S;  // channel stride
constexpr int OUT = 191;                  // output grid side

constexpr int TH = 8, TW = 32;            // output tile (h, w) per block
constexpr int NT = TH * TW;               // 256 threads
constexpr int INR = TH + 3;               // 11 input rows  (h0-1 .. h0+9)
constexpr int INC = TW + 3;               // 35 input cols  (w0-1 .. w0+33)
constexpr int NPL = INR * INC;            // 385 floats per channel plane-tile
constexpr int WSR = TH + 2;               // 10 diff rows (qh = h0-1 .. h0+8)
constexpr int NWS = WSR * TW;             // 320
constexpr int DCH = 4, DPER = 48;         // 4 depth chunks x 48 outputs
constexpr int GX = 6, GY = 24;
constexpr int NBLOCKS = GX * GY * DCH;    // 576

__device__ double g_part[NBLOCKS];

__global__ void finalize_kernel(float* out) {
    __shared__ double wsum[8];
    int tid = threadIdx.x;
    double s = 0.0;
    for (int i = tid; i < NBLOCKS; i += 256) s += g_part[i];
#pragma unroll
    for (int o = 16; o > 0; o >>= 1) s += __shfl_down_sync(0xffffffffu, s, o);
    int lane = tid & 31, warp = tid >> 5;
    if (lane == 0) wsum[warp] = s;
    __syncthreads();
    if (warp == 0) {
        double v = (lane < 8) ? wsum[lane] : 0.0;
#pragma unroll
        for (int o = 4; o > 0; o >>= 1) v += __shfl_down_sync(0xffffffffu, v, o);
        if (lane == 0) out[0] = (float)(v / ((double)OUT * OUT * OUT));
    }
}

__global__ __launch_bounds__(NT, 4)
void nh_kernel(const float* __restrict__ yp)
{
    __shared__ float s_in[2][3 * NPL];    // ping-pong input plane tiles
    __shared__ float s_ws[9 * NWS];       // W-summed diff fields, field-major
    __shared__ float s_red[NT / 32];

    const int tid = threadIdx.x;
    const int w   = tid & 31;             // lane -> w within tile
    const int wr  = tid >> 5;             // warp -> h within tile (0..7)
    const int w0  = blockIdx.x * TW;
    const int h0  = blockIdx.y * TH;
    const int od0 = blockIdx.z * DPER;
    const int od1 = min(OUT, od0 + DPER);

    // ---- fixed per-lane masks ----
    float mw0, mw1, mw2;
    {
        int qw = w0 + w - 1;
        mw0 = (qw >= 0     && qw < OUT)     ? 1.f : 0.f;
        mw1 = (qw + 1 >= 0 && qw + 1 < OUT) ? 1.f : 0.f;
        mw2 = (qw + 2 >= 0 && qw + 2 < OUT) ? 1.f : 0.f;
    }
    const float eo = ((h0 + wr < OUT) && (w0 + w < OUT)) ? 1.f : 0.f;

    // ---- plane loader: global plane p -> s_in[p & 1] (zero-padded) ----
    auto load_plane = [&](int p) {
        float* dst = s_in[p & 1];
        const float* src = yp + (size_t)p * SD;
#pragma unroll
        for (int c = 0; c < 3; ++c) {
            const float* sc = src + (size_t)c * CS;
            float* dc = dst + c * NPL;
#pragma unroll
            for (int k = 0; k < 2; ++k) {
                int r = wr + 8 * k;                   // 0..15, need r<11
                if (r < INR) {
                    int gh = h0 - 1 + r;
                    bool hok = (unsigned)gh < (unsigned)S;
                    const float* row = sc + gh * S;
                    int gw = w0 - 1 + w;
                    float v0 = 0.f;
                    if (hok && (unsigned)gw < (unsigned)S) v0 = row[gw];
                    dc[r * INC + w] = v0;
                    if (w < 3) {                      // cols 32..34
                        float v1 = 0.f;
                        int gw1 = gw + 32;
                        if (hok && (unsigned)gw1 < (unsigned)S) v1 = row[gw1];
                        dc[r * INC + w + 32] = v1;
                    }
                }
            }
        }
    };

    // rolling plane-sums; r = c*3 + t (t: 0=D-diff, 1=H-diff, 2=W-diff)
    float psA[9], psB[9];
#pragma unroll
    for (int r = 0; r < 9; ++r) { psA[r] = 0.f; psB[r] = 0.f; }

    if (od0 > 0) load_plane(od0 - 1);     // plane for the first stage-2 read

    float acc = 0.f;
    const float inv27 = 1.f / 27.f;

    for (int dd = od0 - 1; dd <= od1; ++dd) {
        const int p = dd + 1;
        if (p < S) load_plane(p);
        __syncthreads();                  // orders prior stage-3 reads before new s_ws writes too

        const bool dok = (dd >= 0) && (dd < OUT);   // block-uniform

        // ---- stage 2: fused diff + W 3-tap sum -> s_ws ----
        if (dok) {
            const float* sOld = s_in[dd & 1];
            const float* sNew = s_in[(dd + 1) & 1];
#pragma unroll
            for (int k = 0; k < 4; ++k) {
                int rowidx = wr + 8 * k;              // 0..31, need < 30
                if (rowidx < 30) {
                    int c  = rowidx / 10;             // const-div -> mul/shift
                    int hh = rowidx - c * 10;
                    int qh = h0 - 1 + hh;
                    float mh = (qh >= 0 && qh < OUT) ? 1.f : 0.f;
                    float m0 = mh * mw0, m1 = mh * mw1, m2 = mh * mw2;
                    int off = c * NPL + hh * INC + w;
                    const float* p0 = sOld + off;
                    const float* pD = sNew + off;
                    float a0 = p0[0], a1 = p0[1], a2 = p0[2], a3 = p0[3];
                    float b0 = p0[INC], b1 = p0[INC + 1], b2 = p0[INC + 2];
                    float c0 = pD[0], c1 = pD[1], c2 = pD[2];
                    float sD = m0 * fabsf(c0 - a0) + m1 * fabsf(c1 - a1) + m2 * fabsf(c2 - a2);
                    float sH = m0 * fabsf(b0 - a0) + m1 * fabsf(b1 - a1) + m2 * fabsf(b2 - a2);
                    float sW = m0 * fabsf(a1 - a0) + m1 * fabsf(a2 - a1) + m2 * fabsf(a3 - a2);
                    int wb = hh * TW + w;
                    s_ws[(c * 3 + 0) * NWS + wb] = sD;
                    s_ws[(c * 3 + 1) * NWS + wb] = sH;
                    s_ws[(c * 3 + 2) * NWS + wb] = sW;
                }
            }
        }
        __syncthreads();

        // ---- stage 3: H 3-tap sum into PS(dd) registers ----
        float psC[9];
        if (dok) {
            const int sb = wr * TW + w;
#pragma unroll
            for (int r = 0; r < 9; ++r) {
                const float* q = s_ws + r * NWS + sb;
                psC[r] = q[0] + q[TW] + q[2 * TW];
            }
        } else {
#pragma unroll
            for (int r = 0; r < 9; ++r) psC[r] = 0.f;
        }

        // ---- emit output depth d = dd-1 ----
        if (dd - 1 >= od0) {              // block-uniform
            float f[9];
#pragma unroll
            for (int r = 0; r < 9; ++r)
                f[r] = (psA[r] + psB[r] + psC[r]) * inv27;
            // channel->role (reference): fx=filt(H-diff), fy=filt(D-diff), fz=filt(W-diff)
            float dxdx = f[4], dydx = f[1], dzdx = f[7];
            float dxdy = f[3], dydy = f[0], dzdy = f[6];
            float dxdz = f[5], dydz = f[2], dzdz = f[8];
            float a11 = dxdx + 1.f, a22 = dydy + 1.f, a33 = dzdz + 1.f;
            float J = a11 * (a22 * a33 - dydz * dzdy)
                    - dxdy * (dydx * a33 - dydz * dzdx)
                    + dxdz * (dydx * dzdy - a22 * dzdx);
            float Tr = a11 * a11 + dxdy * dxdy + dxdz * dxdz
                     + dydx * dydx + a22 * a22 + dydz * dydz
                     + dzdx * dzdx + dzdy * dzdy + a33 * a33;
            float stretch = Tr * __expf(1.f - J) - 3.f;
            float jm1 = J - 1.f;
            // mu=1, lam=5; mu<-1/6; lam<-5/(5+1/6)=30/31 => mu/2=1/12, lam/2=15/31
            acc += eo * ((1.f / 12.f) * stretch + (15.f / 31.f) * (jm1 * jm1));
        }

        // ---- roll ----
#pragma unroll
        for (int r = 0; r < 9; ++r) { psA[r] = psB[r]; psB[r] = psC[r]; }
    }

    // ---- block reduction -> per-block partial ----
#pragma unroll
    for (int o = 16; o > 0; o >>= 1)
        acc += __shfl_down_sync(0xffffffffu, acc, o);
    if (w == 0) s_red[wr] = acc;
    __syncthreads();
    if (wr == 0) {
        float v = (w < NT / 32) ? s_red[w] : 0.f;
#pragma unroll
        for (int o = 4; o > 0; o >>= 1)
            v += __shfl_down_sync(0xffffffffu, v, o);
        if (w == 0) {
            int bid = blockIdx.x + GX * (blockIdx.y + GY * blockIdx.z);
            g_part[bid] = (double)v;
        }
    }
}

extern "C" void kernel_launch(void* const* d_in, const int* in_sizes, int n_in,
                              void* d_out, int out_size)
{
    const float* yp = (const float*)d_in[0];   // y_pred [1,3,192,192,192]
    float* out = (float*)d_out;                // scalar output

    dim3 grid(GX, GY, DCH);                    // 6 x 24 x 4 = 576 blocks (one wave @ occ 4)
    nh_kernel<<<grid, NT>>>(yp);
    finalize_kernel<<<1, 256>>>(out);
}